// round 5
// baseline (speedup 1.0000x reference)
#include <cuda_runtime.h>
#include <cuda_bf16.h>

#define NN 40000
#define EE 640000
#define FD 128
#define HH 4
#define LL 3
#define NEG 0.2f
#define BNEPS 1e-5f

// ---------------- scratch (device globals; no allocations allowed) ----------
__device__ __align__(16) __nv_bfloat16 g_hb[NN * FD];  // h rows in bf16 [N,128]
__device__ __align__(16) float g_x  [NN * FD];     // layer input ping    [N,128]
__device__ __align__(16) float g_as [NN * HH];     // per-head src logits [N,4]
__device__ __align__(16) float g_ad [NN * HH];     // per-head dst logits [N,4]
__device__ int   g_cnt [NN];                        // in-degree counts
__device__ int   g_rs  [NN + 1];                    // CSR row starts
__device__ int   g_woff[NN];                        // scatter cursors
__device__ int   g_csrc[EE];                        // CSR src node ids

__device__ __forceinline__ float lrelu(float v) { return v > 0.f ? v : NEG * v; }

__device__ __forceinline__ unsigned int f2tf(float v) {
    unsigned int r;
    asm("cvt.rna.tf32.f32 %0, %1;" : "=r"(r) : "f"(v));
    return r;
}

__device__ __forceinline__ void mma_tf32(float c[4],
                                         unsigned int a0, unsigned int a1,
                                         unsigned int a2, unsigned int a3,
                                         unsigned int b0, unsigned int b1) {
    asm volatile("mma.sync.aligned.m16n8k8.row.col.f32.tf32.tf32.f32 "
                 "{%0,%1,%2,%3}, {%4,%5,%6,%7}, {%8,%9}, {%0,%1,%2,%3};"
                 : "+f"(c[0]), "+f"(c[1]), "+f"(c[2]), "+f"(c[3])
                 : "r"(a0), "r"(a1), "r"(a2), "r"(a3), "r"(b0), "r"(b1));
}

// ---------------- CSR build --------------------------------------------------
__global__ void k_zero_cnt() {
    int i = blockIdx.x * blockDim.x + threadIdx.x;
    if (i < NN) g_cnt[i] = 0;
}

__global__ void k_hist(const int* __restrict__ dst) {
    int i = blockIdx.x * blockDim.x + threadIdx.x;
    if (i >= EE / 4) return;
    const int4 d = ((const int4*)dst)[i];
    atomicAdd(&g_cnt[d.x], 1);
    atomicAdd(&g_cnt[d.y], 1);
    atomicAdd(&g_cnt[d.z], 1);
    atomicAdd(&g_cnt[d.w], 1);
}

__global__ void k_scan() {
    __shared__ int part[1024];
    const int t = threadIdx.x;
    const int CH = 40;
    const int base = t * CH;
    int s = 0;
#pragma unroll 8
    for (int i = 0; i < CH; i++) {
        int idx = base + i;
        if (idx < NN) s += g_cnt[idx];
    }
    part[t] = s;
    __syncthreads();
    for (int o = 1; o < 1024; o <<= 1) {
        int v = (t >= o) ? part[t - o] : 0;
        __syncthreads();
        part[t] += v;
        __syncthreads();
    }
    int excl = (t == 0) ? 0 : part[t - 1];
    for (int i = 0; i < CH; i++) {
        int idx = base + i;
        if (idx < NN) {
            g_rs[idx]   = excl;
            g_woff[idx] = excl;
            excl += g_cnt[idx];
        }
    }
    if (t == 1023) g_rs[NN] = part[1023];
}

__global__ void k_scatter(const int* __restrict__ src, const int* __restrict__ dst) {
    int i = blockIdx.x * blockDim.x + threadIdx.x;
    if (i >= EE / 4) return;
    const int4 d = ((const int4*)dst)[i];
    const int4 s = ((const int4*)src)[i];
    g_csrc[atomicAdd(&g_woff[d.x], 1)] = s.x;
    g_csrc[atomicAdd(&g_woff[d.y], 1)] = s.y;
    g_csrc[atomicAdd(&g_woff[d.z], 1)] = s.z;
    g_csrc[atomicAdd(&g_woff[d.w], 1)] = s.w;
}

// ---------------- K1: h = x @ W via 3xTF32 tensor-core MMA ------------------
// block 256 threads / 8 warps; block tile 128x128; warp tile m16 x n128.
// K chunked by 16 through smem; hi/lo tf32 split computed at load time.
#define AP 20     // As row pad (conflict-free frag reads)
#define BP 132    // Bs row pad
__global__ __launch_bounds__(256) void k_gemm(const float* __restrict__ x_in,
                                              int layer,
                                              const float* __restrict__ W,
                                              const float* __restrict__ as_w,
                                              const float* __restrict__ ad_w) {
    const float* x = (layer == 0) ? x_in : g_x;
    __shared__ unsigned int As_hi[128][AP], As_lo[128][AP];
    __shared__ unsigned int Bs_hi[16][BP],  Bs_lo[16][BP];

    const int tid  = threadIdx.x;
    const int lane = tid & 31;
    const int wid  = tid >> 5;
    const int g    = lane >> 2;      // row group in fragment
    const int t    = lane & 3;       // col group in fragment
    const int wm   = wid * 16;       // warp row offset in block tile
    const int row0 = blockIdx.x * 128;

    // loader indices
    const int xrow = tid >> 1;                // 0..127
    const int xk   = (tid & 1) * 8;           // 0 or 8
    const int wkr  = tid >> 4;                // 0..15
    const int wnc  = (tid & 15) * 8;          // 0..120

    float c[16][4];
#pragma unroll
    for (int i = 0; i < 16; i++)
#pragma unroll
        for (int j = 0; j < 4; j++) c[i][j] = 0.f;

    const int grow = min(row0 + xrow, NN - 1);

    for (int k0 = 0; k0 < FD; k0 += 16) {
        const float4 v0 = *(const float4*)&x[grow * FD + k0 + xk];
        const float4 v1 = *(const float4*)&x[grow * FD + k0 + xk + 4];
        const float4 w0 = *(const float4*)&W[(k0 + wkr) * FD + wnc];
        const float4 w1 = *(const float4*)&W[(k0 + wkr) * FD + wnc + 4];
        __syncthreads();
        {
            const float xv[8] = {v0.x, v0.y, v0.z, v0.w, v1.x, v1.y, v1.z, v1.w};
#pragma unroll
            for (int i = 0; i < 8; i++) {
                unsigned int h = f2tf(xv[i]);
                As_hi[xrow][xk + i] = h;
                As_lo[xrow][xk + i] = f2tf(xv[i] - __uint_as_float(h));
            }
            const float wv[8] = {w0.x, w0.y, w0.z, w0.w, w1.x, w1.y, w1.z, w1.w};
#pragma unroll
            for (int i = 0; i < 8; i++) {
                unsigned int h = f2tf(wv[i]);
                Bs_hi[wkr][wnc + i] = h;
                Bs_lo[wkr][wnc + i] = f2tf(wv[i] - __uint_as_float(h));
            }
        }
        __syncthreads();

#pragma unroll
        for (int ks = 0; ks < 2; ks++) {
            const int kc = ks * 8;
            const unsigned int ah0 = As_hi[wm + g][kc + t];
            const unsigned int ah1 = As_hi[wm + g + 8][kc + t];
            const unsigned int ah2 = As_hi[wm + g][kc + t + 4];
            const unsigned int ah3 = As_hi[wm + g + 8][kc + t + 4];
            const unsigned int al0 = As_lo[wm + g][kc + t];
            const unsigned int al1 = As_lo[wm + g + 8][kc + t];
            const unsigned int al2 = As_lo[wm + g][kc + t + 4];
            const unsigned int al3 = As_lo[wm + g + 8][kc + t + 4];
#pragma unroll
            for (int nf = 0; nf < 16; nf++) {
                const int bn = nf * 8 + g;
                const unsigned int bh0 = Bs_hi[kc + t][bn];
                const unsigned int bh1 = Bs_hi[kc + t + 4][bn];
                const unsigned int bl0 = Bs_lo[kc + t][bn];
                const unsigned int bl1 = Bs_lo[kc + t + 4][bn];
                mma_tf32(c[nf], ah0, ah1, ah2, ah3, bh0, bh1);
                mma_tf32(c[nf], al0, al1, al2, al3, bh0, bh1);
                mma_tf32(c[nf], ah0, ah1, ah2, ah3, bl0, bl1);
            }
        }
    }

    // ---- epilogue: store bf16 h rows ----
    const int rA = row0 + wm + g;
    const int rB = rA + 8;
#pragma unroll
    for (int nf = 0; nf < 16; nf++) {
        const int col = nf * 8 + t * 2;
        if (rA < NN) {
            __nv_bfloat162 p = __floats2bfloat162_rn(c[nf][0], c[nf][1]);
            *(__nv_bfloat162*)&g_hb[rA * FD + col] = p;
        }
        if (rB < NN) {
            __nv_bfloat162 p = __floats2bfloat162_rn(c[nf][2], c[nf][3]);
            *(__nv_bfloat162*)&g_hb[rB * FD + col] = p;
        }
    }

    // ---- fused attention logits: head h covers cols [h*32, h*32+32) = frags 4h..4h+3
#pragma unroll
    for (int h = 0; h < HH; h++) {
        float sA0 = 0.f, sD0 = 0.f, sA1 = 0.f, sD1 = 0.f;
#pragma unroll
        for (int q = 0; q < 4; q++) {
            const int nf  = h * 4 + q;
            const int col = nf * 8 + t * 2;
            const float a0 = as_w[col], a1 = as_w[col + 1];
            const float d0 = ad_w[col], d1 = ad_w[col + 1];
            sA0 += c[nf][0] * a0 + c[nf][1] * a1;
            sD0 += c[nf][0] * d0 + c[nf][1] * d1;
            sA1 += c[nf][2] * a0 + c[nf][3] * a1;
            sD1 += c[nf][2] * d0 + c[nf][3] * d1;
        }
        // reduce over the 4 lanes of this row group (adjacent lanes 4g..4g+3)
        sA0 += __shfl_xor_sync(0xffffffffu, sA0, 1);
        sD0 += __shfl_xor_sync(0xffffffffu, sD0, 1);
        sA1 += __shfl_xor_sync(0xffffffffu, sA1, 1);
        sD1 += __shfl_xor_sync(0xffffffffu, sD1, 1);
        sA0 += __shfl_xor_sync(0xffffffffu, sA0, 2);
        sD0 += __shfl_xor_sync(0xffffffffu, sD0, 2);
        sA1 += __shfl_xor_sync(0xffffffffu, sA1, 2);
        sD1 += __shfl_xor_sync(0xffffffffu, sD1, 2);
        if (t == 0) {
            if (rA < NN) { g_as[rA * HH + h] = sA0; g_ad[rA * HH + h] = sD0; }
            if (rB < NN) { g_as[rB * HH + h] = sA1; g_ad[rB * HH + h] = sD1; }
        }
    }
}

// ---------------- K2: single-pass attention + aggregation + epilogue --------
__global__ __launch_bounds__(256) void k_attn(int last,
                           const float* __restrict__ bias,
                           const float* __restrict__ gamma,
                           const float* __restrict__ beta,
                           const float* __restrict__ mean,
                           const float* __restrict__ var,
                           const float* __restrict__ w_out,
                           const float* __restrict__ b_out,
                           float* __restrict__ out) {
    __shared__ float sw[8][32 * 4];
    __shared__ int   ssrc[8][32];
    const int n    = (blockIdx.x * blockDim.x + threadIdx.x) >> 5;
    const int wid  = threadIdx.x >> 5;
    const int lane = threadIdx.x & 31;
    if (n >= NN) return;
    const int rs = g_rs[n], re = g_rs[n + 1];
    const int head = lane >> 3;

    const float4 adv = *(const float4*)&g_ad[n * HH];
    const float4 asn = *(const float4*)&g_as[n * HH];

    const float ws0 = __expf(lrelu(asn.x + adv.x));
    const float ws1 = __expf(lrelu(asn.y + adv.y));
    const float ws2 = __expf(lrelu(asn.z + adv.z));
    const float ws3 = __expf(lrelu(asn.w + adv.w));
    const float w_self = (head == 0) ? ws0 : (head == 1) ? ws1 : (head == 2) ? ws2 : ws3;

    float4 acc;
    {
        const uint2 hv = *(const uint2*)&g_hb[n * FD + lane * 4];
        const float2 f0 = __bfloat1622float2(*(const __nv_bfloat162*)&hv.x);
        const float2 f1 = __bfloat1622float2(*(const __nv_bfloat162*)&hv.y);
        acc.x = f0.x * w_self; acc.y = f0.y * w_self;
        acc.z = f1.x * w_self; acc.w = f1.y * w_self;
    }

    float p0 = 0.f, p1 = 0.f, p2 = 0.f, p3 = 0.f;

    for (int base = rs; base < re; base += 32) {
        const int j = base + lane;
        float4 w = make_float4(0.f, 0.f, 0.f, 0.f);
        int sreg = 0;
        if (j < re) {
            sreg = g_csrc[j];
            const float4 as = *(const float4*)&g_as[sreg * HH];
            w.x = __expf(lrelu(as.x + adv.x));
            w.y = __expf(lrelu(as.y + adv.y));
            w.z = __expf(lrelu(as.z + adv.z));
            w.w = __expf(lrelu(as.w + adv.w));
            p0 += w.x; p1 += w.y; p2 += w.z; p3 += w.w;
        }
        __syncwarp();
        *(float4*)&sw[wid][lane * 4] = w;
        ssrc[wid][lane] = sreg;
        __syncwarp();
        const int cnt = min(32, re - base);
        int jj = 0;
        for (; jj + 4 <= cnt; jj += 4) {
            const int s0 = ssrc[wid][jj + 0];
            const int s1 = ssrc[wid][jj + 1];
            const int s2 = ssrc[wid][jj + 2];
            const int s3 = ssrc[wid][jj + 3];
            const float w0 = sw[wid][(jj + 0) * 4 + head];
            const float w1 = sw[wid][(jj + 1) * 4 + head];
            const float w2 = sw[wid][(jj + 2) * 4 + head];
            const float w3 = sw[wid][(jj + 3) * 4 + head];
            const uint2 v0 = *(const uint2*)&g_hb[s0 * FD + lane * 4];
            const uint2 v1 = *(const uint2*)&g_hb[s1 * FD + lane * 4];
            const uint2 v2 = *(const uint2*)&g_hb[s2 * FD + lane * 4];
            const uint2 v3 = *(const uint2*)&g_hb[s3 * FD + lane * 4];
            float2 a0 = __bfloat1622float2(*(const __nv_bfloat162*)&v0.x);
            float2 b0 = __bfloat1622float2(*(const __nv_bfloat162*)&v0.y);
            acc.x += a0.x * w0; acc.y += a0.y * w0; acc.z += b0.x * w0; acc.w += b0.y * w0;
            float2 a1 = __bfloat1622float2(*(const __nv_bfloat162*)&v1.x);
            float2 b1 = __bfloat1622float2(*(const __nv_bfloat162*)&v1.y);
            acc.x += a1.x * w1; acc.y += a1.y * w1; acc.z += b1.x * w1; acc.w += b1.y * w1;
            float2 a2 = __bfloat1622float2(*(const __nv_bfloat162*)&v2.x);
            float2 b2 = __bfloat1622float2(*(const __nv_bfloat162*)&v2.y);
            acc.x += a2.x * w2; acc.y += a2.y * w2; acc.z += b2.x * w2; acc.w += b2.y * w2;
            float2 a3 = __bfloat1622float2(*(const __nv_bfloat162*)&v3.x);
            float2 b3 = __bfloat1622float2(*(const __nv_bfloat162*)&v3.y);
            acc.x += a3.x * w3; acc.y += a3.y * w3; acc.z += b3.x * w3; acc.w += b3.y * w3;
        }
        for (; jj < cnt; jj++) {
            const int   s  = ssrc[wid][jj];
            const float ww = sw[wid][jj * 4 + head];
            const uint2 v  = *(const uint2*)&g_hb[s * FD + lane * 4];
            float2 a = __bfloat1622float2(*(const __nv_bfloat162*)&v.x);
            float2 b = __bfloat1622float2(*(const __nv_bfloat162*)&v.y);
            acc.x += a.x * ww; acc.y += a.y * ww;
            acc.z += b.x * ww; acc.w += b.y * ww;
        }
    }

#pragma unroll
    for (int o = 16; o > 0; o >>= 1) {
        p0 += __shfl_xor_sync(0xffffffffu, p0, o);
        p1 += __shfl_xor_sync(0xffffffffu, p1, o);
        p2 += __shfl_xor_sync(0xffffffffu, p2, o);
        p3 += __shfl_xor_sync(0xffffffffu, p3, o);
    }
    const float denom = ((head == 0) ? p0 : (head == 1) ? p1 : (head == 2) ? p2 : p3)
                        + w_self;
    const float inv = 1.f / (denom + 1e-16f);
    acc.x *= inv; acc.y *= inv; acc.z *= inv; acc.w *= inv;

    const int c4 = lane * 4;
    const float4 b  = *(const float4*)&bias[c4];
    const float4 g  = *(const float4*)&gamma[c4];
    const float4 bt = *(const float4*)&beta[c4];
    const float4 mm = *(const float4*)&mean[c4];
    const float4 vr = *(const float4*)&var[c4];
    float4 o;
    o.x = fmaxf((acc.x + b.x - mm.x) * rsqrtf(vr.x + BNEPS) * g.x + bt.x, 0.f);
    o.y = fmaxf((acc.y + b.y - mm.y) * rsqrtf(vr.y + BNEPS) * g.y + bt.y, 0.f);
    o.z = fmaxf((acc.z + b.z - mm.z) * rsqrtf(vr.z + BNEPS) * g.z + bt.z, 0.f);
    o.w = fmaxf((acc.w + b.w - mm.w) * rsqrtf(vr.w + BNEPS) * g.w + bt.w, 0.f);

    if (!last) {
        *(float4*)&g_x[n * FD + c4] = o;
    } else {
        const float4 wv = *(const float4*)&w_out[c4];
        float sum = o.x * wv.x + o.y * wv.y + o.z * wv.z + o.w * wv.w;
#pragma unroll
        for (int off = 16; off > 0; off >>= 1)
            sum += __shfl_down_sync(0xffffffffu, sum, off);
        if (lane == 0) out[n] = sum + b_out[0];
    }
}

// ---------------- launcher ---------------------------------------------------
extern "C" void kernel_launch(void* const* d_in, const int* in_sizes, int n_in,
                              void* d_out, int out_size) {
    const float* x       = (const float*)d_in[0];
    const int*   ei      = (const int*)  d_in[1];
    const float* W       = (const float*)d_in[2];
    const float* att_src = (const float*)d_in[3];
    const float* att_dst = (const float*)d_in[4];
    const float* bias    = (const float*)d_in[5];
    const float* gamma   = (const float*)d_in[6];
    const float* beta    = (const float*)d_in[7];
    const float* mean    = (const float*)d_in[8];
    const float* var     = (const float*)d_in[9];
    const float* w_out   = (const float*)d_in[10];
    const float* b_out   = (const float*)d_in[11];

    const int* src = ei;
    const int* dst = ei + EE;

    const int WGRID = (NN * 32 + 255) / 256;
    const int GGRID = (NN + 127) / 128;

    k_zero_cnt<<<(NN + 255) / 256, 256>>>();
    k_hist    <<<(EE / 4 + 255) / 256, 256>>>(dst);
    k_scan    <<<1, 1024>>>();
    k_gemm    <<<GGRID, 256>>>(x, 0, W, att_src, att_dst);        // sampled launch
    k_scatter <<<(EE / 4 + 255) / 256, 256>>>(src, dst);

    for (int l = 0; l < LL; l++) {
        if (l > 0)
            k_gemm<<<GGRID, 256>>>(x, l, W + l * FD * FD,
                                   att_src + l * FD, att_dst + l * FD);
        k_attn<<<WGRID, 256>>>(l == LL - 1,
                               bias + l * FD, gamma + l * FD, beta + l * FD,
                               mean + l * FD, var + l * FD,
                               w_out, b_out, (float*)d_out);
    }
}

// round 6
// speedup vs baseline: 1.0149x; 1.0149x over previous
#include <cuda_runtime.h>
#include <cuda_bf16.h>

#define NN 40000
#define EE 640000
#define FD 128
#define HH 4
#define LL 3
#define NEG 0.2f
#define BNEPS 1e-5f

// ---------------- scratch (device globals; no allocations allowed) ----------
__device__ __align__(16) __nv_bfloat16 g_hb[NN * FD];  // h rows in bf16 [N,128]
__device__ __align__(16) float g_x  [NN * FD];     // layer input ping    [N,128]
__device__ __align__(16) float g_as [NN * HH];     // per-head src logits [N,4]
__device__ __align__(16) float g_ad [NN * HH];     // per-head dst logits [N,4]
__device__ int   g_cnt [NN];                        // in-degree counts
__device__ int   g_rs  [NN + 1];                    // CSR row starts
__device__ int   g_woff[NN];                        // scatter cursors
__device__ int   g_csrc[EE];                        // CSR src node ids

__device__ __forceinline__ float lrelu(float v) { return v > 0.f ? v : NEG * v; }

__device__ __forceinline__ unsigned int f2tf(float v) {
    unsigned int r;
    asm("cvt.rna.tf32.f32 %0, %1;" : "=r"(r) : "f"(v));
    return r;
}

__device__ __forceinline__ uint2 split_tf(float v) {
    uint2 r;
    r.x = f2tf(v);
    r.y = f2tf(v - __uint_as_float(r.x));
    return r;
}

__device__ __forceinline__ void mma_tf32(float c[4],
                                         unsigned int a0, unsigned int a1,
                                         unsigned int a2, unsigned int a3,
                                         unsigned int b0, unsigned int b1) {
    asm volatile("mma.sync.aligned.m16n8k8.row.col.f32.tf32.tf32.f32 "
                 "{%0,%1,%2,%3}, {%4,%5,%6,%7}, {%8,%9}, {%0,%1,%2,%3};"
                 : "+f"(c[0]), "+f"(c[1]), "+f"(c[2]), "+f"(c[3])
                 : "r"(a0), "r"(a1), "r"(a2), "r"(a3), "r"(b0), "r"(b1));
}

// ---------------- CSR build --------------------------------------------------
__global__ void k_zero_cnt() {
    int i = blockIdx.x * blockDim.x + threadIdx.x;
    if (i < NN) g_cnt[i] = 0;
}

__global__ void k_hist(const int* __restrict__ dst) {
    int i = blockIdx.x * blockDim.x + threadIdx.x;
    if (i >= EE / 4) return;
    const int4 d = ((const int4*)dst)[i];
    atomicAdd(&g_cnt[d.x], 1);
    atomicAdd(&g_cnt[d.y], 1);
    atomicAdd(&g_cnt[d.z], 1);
    atomicAdd(&g_cnt[d.w], 1);
}

__global__ void k_scan() {
    __shared__ int part[1024];
    const int t = threadIdx.x;
    const int CH = 40;
    const int base = t * CH;
    int s = 0;
#pragma unroll 8
    for (int i = 0; i < CH; i++) {
        int idx = base + i;
        if (idx < NN) s += g_cnt[idx];
    }
    part[t] = s;
    __syncthreads();
    for (int o = 1; o < 1024; o <<= 1) {
        int v = (t >= o) ? part[t - o] : 0;
        __syncthreads();
        part[t] += v;
        __syncthreads();
    }
    int excl = (t == 0) ? 0 : part[t - 1];
    for (int i = 0; i < CH; i++) {
        int idx = base + i;
        if (idx < NN) {
            g_rs[idx]   = excl;
            g_woff[idx] = excl;
            excl += g_cnt[idx];
        }
    }
    if (t == 1023) g_rs[NN] = part[1023];
}

__global__ void k_scatter(const int* __restrict__ src, const int* __restrict__ dst) {
    int i = blockIdx.x * blockDim.x + threadIdx.x;
    if (i >= EE / 4) return;
    const int4 d = ((const int4*)dst)[i];
    const int4 s = ((const int4*)src)[i];
    g_csrc[atomicAdd(&g_woff[d.x], 1)] = s.x;
    g_csrc[atomicAdd(&g_woff[d.y], 1)] = s.y;
    g_csrc[atomicAdd(&g_woff[d.z], 1)] = s.z;
    g_csrc[atomicAdd(&g_woff[d.w], 1)] = s.w;
}

// ---------------- K1: h = x @ W via 3xTF32 MMA (hi/lo interleaved uint2) ----
// block 256 threads / 8 warps; block tile 256x128; warp tile m32 x n128.
// K chunked by 8; As[m][k] stride 12 uint2, Bs[k][n] stride 132 uint2 --
// both conflict-free for fragment reads (half-warp phase analysis).
#define ASTRIDE 12
#define BSTRIDE 132
__global__ __launch_bounds__(256) void k_gemm(const float* __restrict__ x_in,
                                              int layer,
                                              const float* __restrict__ W,
                                              const float* __restrict__ as_w,
                                              const float* __restrict__ ad_w) {
    const float* x = (layer == 0) ? x_in : g_x;
    __shared__ uint2 As[256][ASTRIDE];
    __shared__ uint2 Bs[8][BSTRIDE];

    const int tid  = threadIdx.x;
    const int lane = tid & 31;
    const int wid  = tid >> 5;
    const int g    = lane >> 2;      // fragment row group
    const int t    = lane & 3;       // fragment col group
    const int wm   = wid * 32;       // warp row offset in block tile
    const int row0 = blockIdx.x * 256;

    // loaders: A -> one row per thread (8 floats/chunk); B -> 4 uint2 per thread
    const int grow = min(row0 + tid, NN - 1);
    const int brow = tid >> 5;                 // k row 0..7
    const int bcol = (tid & 31) * 4;           // n col quad

    float c[2][16][4];
#pragma unroll
    for (int m = 0; m < 2; m++)
#pragma unroll
        for (int i = 0; i < 16; i++)
#pragma unroll
            for (int j = 0; j < 4; j++) c[m][i][j] = 0.f;

    // prefetch chunk 0
    float4 va0 = *(const float4*)&x[grow * FD + 0];
    float4 va1 = *(const float4*)&x[grow * FD + 4];
    float4 vb0 = *(const float4*)&W[brow * FD + bcol];

    for (int k0 = 0; k0 < FD; k0 += 8) {
        __syncthreads();
        {
            uint2 r[8];
            r[0] = split_tf(va0.x); r[1] = split_tf(va0.y);
            r[2] = split_tf(va0.z); r[3] = split_tf(va0.w);
            r[4] = split_tf(va1.x); r[5] = split_tf(va1.y);
            r[6] = split_tf(va1.z); r[7] = split_tf(va1.w);
            *(uint4*)&As[tid][0] = *(uint4*)&r[0];
            *(uint4*)&As[tid][2] = *(uint4*)&r[2];
            *(uint4*)&As[tid][4] = *(uint4*)&r[4];
            *(uint4*)&As[tid][6] = *(uint4*)&r[6];
            uint2 q[4];
            q[0] = split_tf(vb0.x); q[1] = split_tf(vb0.y);
            q[2] = split_tf(vb0.z); q[3] = split_tf(vb0.w);
            *(uint4*)&Bs[brow][bcol]     = *(uint4*)&q[0];
            *(uint4*)&Bs[brow][bcol + 2] = *(uint4*)&q[2];
        }
        __syncthreads();

        if (k0 + 8 < FD) {   // prefetch next chunk under the MMAs
            va0 = *(const float4*)&x[grow * FD + k0 + 8];
            va1 = *(const float4*)&x[grow * FD + k0 + 12];
            vb0 = *(const float4*)&W[(k0 + 8 + brow) * FD + bcol];
        }

        uint2 a0[2], a1[2], a2[2], a3[2];
#pragma unroll
        for (int m = 0; m < 2; m++) {
            const int mb = wm + m * 16;
            a0[m] = As[mb + g][t];
            a1[m] = As[mb + g + 8][t];
            a2[m] = As[mb + g][t + 4];
            a3[m] = As[mb + g + 8][t + 4];
        }
#pragma unroll
        for (int nf = 0; nf < 16; nf++) {
            const int bn = nf * 8 + g;
            const uint2 b0 = Bs[t][bn];
            const uint2 b1 = Bs[t + 4][bn];
#pragma unroll
            for (int m = 0; m < 2; m++) {
                mma_tf32(c[m][nf], a0[m].x, a1[m].x, a2[m].x, a3[m].x, b0.x, b1.x);
                mma_tf32(c[m][nf], a0[m].y, a1[m].y, a2[m].y, a3[m].y, b0.x, b1.x);
                mma_tf32(c[m][nf], a0[m].x, a1[m].x, a2[m].x, a3[m].x, b0.y, b1.y);
            }
        }
    }

    // ---- epilogue: bf16 h rows + fused attention logits ----
#pragma unroll
    for (int m = 0; m < 2; m++) {
        const int rA = row0 + wm + m * 16 + g;
        const int rB = rA + 8;
#pragma unroll
        for (int nf = 0; nf < 16; nf++) {
            const int col = nf * 8 + t * 2;
            if (rA < NN) {
                __nv_bfloat162 p = __floats2bfloat162_rn(c[m][nf][0], c[m][nf][1]);
                *(__nv_bfloat162*)&g_hb[rA * FD + col] = p;
            }
            if (rB < NN) {
                __nv_bfloat162 p = __floats2bfloat162_rn(c[m][nf][2], c[m][nf][3]);
                *(__nv_bfloat162*)&g_hb[rB * FD + col] = p;
            }
        }
#pragma unroll
        for (int h = 0; h < HH; h++) {
            float sA0 = 0.f, sD0 = 0.f, sA1 = 0.f, sD1 = 0.f;
#pragma unroll
            for (int q = 0; q < 4; q++) {
                const int nf  = h * 4 + q;
                const int col = nf * 8 + t * 2;
                const float a0 = as_w[col], a1 = as_w[col + 1];
                const float d0 = ad_w[col], d1 = ad_w[col + 1];
                sA0 += c[m][nf][0] * a0 + c[m][nf][1] * a1;
                sD0 += c[m][nf][0] * d0 + c[m][nf][1] * d1;
                sA1 += c[m][nf][2] * a0 + c[m][nf][3] * a1;
                sD1 += c[m][nf][2] * d0 + c[m][nf][3] * d1;
            }
            sA0 += __shfl_xor_sync(0xffffffffu, sA0, 1);
            sD0 += __shfl_xor_sync(0xffffffffu, sD0, 1);
            sA1 += __shfl_xor_sync(0xffffffffu, sA1, 1);
            sD1 += __shfl_xor_sync(0xffffffffu, sD1, 1);
            sA0 += __shfl_xor_sync(0xffffffffu, sA0, 2);
            sD0 += __shfl_xor_sync(0xffffffffu, sD0, 2);
            sA1 += __shfl_xor_sync(0xffffffffu, sA1, 2);
            sD1 += __shfl_xor_sync(0xffffffffu, sD1, 2);
            if (t == 0) {
                if (rA < NN) { g_as[rA * HH + h] = sA0; g_ad[rA * HH + h] = sD0; }
                if (rB < NN) { g_as[rB * HH + h] = sA1; g_ad[rB * HH + h] = sD1; }
            }
        }
    }
}

// ---------------- K2: single-pass attention + aggregation + epilogue --------
__global__ __launch_bounds__(256) void k_attn(int last,
                           const float* __restrict__ bias,
                           const float* __restrict__ gamma,
                           const float* __restrict__ beta,
                           const float* __restrict__ mean,
                           const float* __restrict__ var,
                           const float* __restrict__ w_out,
                           const float* __restrict__ b_out,
                           float* __restrict__ out) {
    __shared__ float sw[8][32 * 4];
    __shared__ int   ssrc[8][32];
    const int n    = (blockIdx.x * blockDim.x + threadIdx.x) >> 5;
    const int wid  = threadIdx.x >> 5;
    const int lane = threadIdx.x & 31;
    if (n >= NN) return;
    const int rs = g_rs[n], re = g_rs[n + 1];
    const int head = lane >> 3;

    const float4 adv = *(const float4*)&g_ad[n * HH];
    const float4 asn = *(const float4*)&g_as[n * HH];

    const float ws0 = __expf(lrelu(asn.x + adv.x));
    const float ws1 = __expf(lrelu(asn.y + adv.y));
    const float ws2 = __expf(lrelu(asn.z + adv.z));
    const float ws3 = __expf(lrelu(asn.w + adv.w));
    const float w_self = (head == 0) ? ws0 : (head == 1) ? ws1 : (head == 2) ? ws2 : ws3;

    float4 acc;
    {
        const uint2 hv = *(const uint2*)&g_hb[n * FD + lane * 4];
        const float2 f0 = __bfloat1622float2(*(const __nv_bfloat162*)&hv.x);
        const float2 f1 = __bfloat1622float2(*(const __nv_bfloat162*)&hv.y);
        acc.x = f0.x * w_self; acc.y = f0.y * w_self;
        acc.z = f1.x * w_self; acc.w = f1.y * w_self;
    }

    float p0 = 0.f, p1 = 0.f, p2 = 0.f, p3 = 0.f;

    for (int base = rs; base < re; base += 32) {
        const int j = base + lane;
        float4 w = make_float4(0.f, 0.f, 0.f, 0.f);
        int sreg = 0;
        if (j < re) {
            sreg = g_csrc[j];
            const float4 as = *(const float4*)&g_as[sreg * HH];
            w.x = __expf(lrelu(as.x + adv.x));
            w.y = __expf(lrelu(as.y + adv.y));
            w.z = __expf(lrelu(as.z + adv.z));
            w.w = __expf(lrelu(as.w + adv.w));
            p0 += w.x; p1 += w.y; p2 += w.z; p3 += w.w;
        }
        __syncwarp();
        *(float4*)&sw[wid][lane * 4] = w;
        ssrc[wid][lane] = sreg;
        __syncwarp();
        const int cnt = min(32, re - base);
        int jj = 0;
        for (; jj + 4 <= cnt; jj += 4) {
            const int s0 = ssrc[wid][jj + 0];
            const int s1 = ssrc[wid][jj + 1];
            const int s2 = ssrc[wid][jj + 2];
            const int s3 = ssrc[wid][jj + 3];
            const float w0 = sw[wid][(jj + 0) * 4 + head];
            const float w1 = sw[wid][(jj + 1) * 4 + head];
            const float w2 = sw[wid][(jj + 2) * 4 + head];
            const float w3 = sw[wid][(jj + 3) * 4 + head];
            const uint2 v0 = *(const uint2*)&g_hb[s0 * FD + lane * 4];
            const uint2 v1 = *(const uint2*)&g_hb[s1 * FD + lane * 4];
            const uint2 v2 = *(const uint2*)&g_hb[s2 * FD + lane * 4];
            const uint2 v3 = *(const uint2*)&g_hb[s3 * FD + lane * 4];
            float2 a0 = __bfloat1622float2(*(const __nv_bfloat162*)&v0.x);
            float2 b0 = __bfloat1622float2(*(const __nv_bfloat162*)&v0.y);
            acc.x += a0.x * w0; acc.y += a0.y * w0; acc.z += b0.x * w0; acc.w += b0.y * w0;
            float2 a1 = __bfloat1622float2(*(const __nv_bfloat162*)&v1.x);
            float2 b1 = __bfloat1622float2(*(const __nv_bfloat162*)&v1.y);
            acc.x += a1.x * w1; acc.y += a1.y * w1; acc.z += b1.x * w1; acc.w += b1.y * w1;
            float2 a2 = __bfloat1622float2(*(const __nv_bfloat162*)&v2.x);
            float2 b2 = __bfloat1622float2(*(const __nv_bfloat162*)&v2.y);
            acc.x += a2.x * w2; acc.y += a2.y * w2; acc.z += b2.x * w2; acc.w += b2.y * w2;
            float2 a3 = __bfloat1622float2(*(const __nv_bfloat162*)&v3.x);
            float2 b3 = __bfloat1622float2(*(const __nv_bfloat162*)&v3.y);
            acc.x += a3.x * w3; acc.y += a3.y * w3; acc.z += b3.x * w3; acc.w += b3.y * w3;
        }
        for (; jj < cnt; jj++) {
            const int   s  = ssrc[wid][jj];
            const float ww = sw[wid][jj * 4 + head];
            const uint2 v  = *(const uint2*)&g_hb[s * FD + lane * 4];
            float2 a = __bfloat1622float2(*(const __nv_bfloat162*)&v.x);
            float2 b = __bfloat1622float2(*(const __nv_bfloat162*)&v.y);
            acc.x += a.x * ww; acc.y += a.y * ww;
            acc.z += b.x * ww; acc.w += b.y * ww;
        }
    }

#pragma unroll
    for (int o = 16; o > 0; o >>= 1) {
        p0 += __shfl_xor_sync(0xffffffffu, p0, o);
        p1 += __shfl_xor_sync(0xffffffffu, p1, o);
        p2 += __shfl_xor_sync(0xffffffffu, p2, o);
        p3 += __shfl_xor_sync(0xffffffffu, p3, o);
    }
    const float denom = ((head == 0) ? p0 : (head == 1) ? p1 : (head == 2) ? p2 : p3)
                        + w_self;
    const float inv = 1.f / (denom + 1e-16f);
    acc.x *= inv; acc.y *= inv; acc.z *= inv; acc.w *= inv;

    const int c4 = lane * 4;
    const float4 b  = *(const float4*)&bias[c4];
    const float4 g  = *(const float4*)&gamma[c4];
    const float4 bt = *(const float4*)&beta[c4];
    const float4 mm = *(const float4*)&mean[c4];
    const float4 vr = *(const float4*)&var[c4];
    float4 o;
    o.x = fmaxf((acc.x + b.x - mm.x) * rsqrtf(vr.x + BNEPS) * g.x + bt.x, 0.f);
    o.y = fmaxf((acc.y + b.y - mm.y) * rsqrtf(vr.y + BNEPS) * g.y + bt.y, 0.f);
    o.z = fmaxf((acc.z + b.z - mm.z) * rsqrtf(vr.z + BNEPS) * g.z + bt.z, 0.f);
    o.w = fmaxf((acc.w + b.w - mm.w) * rsqrtf(vr.w + BNEPS) * g.w + bt.w, 0.f);

    if (!last) {
        *(float4*)&g_x[n * FD + c4] = o;
    } else {
        const float4 wv = *(const float4*)&w_out[c4];
        float sum = o.x * wv.x + o.y * wv.y + o.z * wv.z + o.w * wv.w;
#pragma unroll
        for (int off = 16; off > 0; off >>= 1)
            sum += __shfl_down_sync(0xffffffffu, sum, off);
        if (lane == 0) out[n] = sum + b_out[0];
    }
}

// ---------------- launcher ---------------------------------------------------
extern "C" void kernel_launch(void* const* d_in, const int* in_sizes, int n_in,
                              void* d_out, int out_size) {
    const float* x       = (const float*)d_in[0];
    const int*   ei      = (const int*)  d_in[1];
    const float* W       = (const float*)d_in[2];
    const float* att_src = (const float*)d_in[3];
    const float* att_dst = (const float*)d_in[4];
    const float* bias    = (const float*)d_in[5];
    const float* gamma   = (const float*)d_in[6];
    const float* beta    = (const float*)d_in[7];
    const float* mean    = (const float*)d_in[8];
    const float* var     = (const float*)d_in[9];
    const float* w_out   = (const float*)d_in[10];
    const float* b_out   = (const float*)d_in[11];

    const int* src = ei;
    const int* dst = ei + EE;

    const int WGRID = (NN * 32 + 255) / 256;
    const int GGRID = (NN + 255) / 256;

    k_zero_cnt<<<(NN + 255) / 256, 256>>>();
    k_hist    <<<(EE / 4 + 255) / 256, 256>>>(dst);
    k_scan    <<<1, 1024>>>();
    k_gemm    <<<GGRID, 256>>>(x, 0, W, att_src, att_dst);        // sampled launch
    k_scatter <<<(EE / 4 + 255) / 256, 256>>>(src, dst);

    for (int l = 0; l < LL; l++) {
        if (l > 0)
            k_gemm<<<GGRID, 256>>>(x, l, W + l * FD * FD,
                                   att_src + l * FD, att_dst + l * FD);
        k_attn<<<WGRID, 256>>>(l == LL - 1,
                               bias + l * FD, gamma + l * FD, beta + l * FD,
                               mean + l * FD, var + l * FD,
                               w_out, b_out, (float*)d_out);
    }
}

// round 7
// speedup vs baseline: 1.2630x; 1.2444x over previous
#include <cuda_runtime.h>
#include <cuda_bf16.h>

#define NN 40000
#define EE 640000
#define FD 128
#define HH 4
#define LL 3
#define NEG 0.2f
#define BNEPS 1e-5f

// ---------------- scratch (device globals; no allocations allowed) ----------
__device__ __align__(16) __nv_bfloat16 g_hb[NN * FD];  // h rows in bf16 [N,128]
__device__ __align__(16) float g_x  [NN * FD];     // layer input ping    [N,128]
__device__ __align__(16) float g_as [NN * HH];     // per-head src logits [N,4]
__device__ __align__(16) float g_ad [NN * HH];     // per-head dst logits [N,4]
__device__ int   g_cnt [NN];                        // in-degree counts
__device__ int   g_rs  [NN + 1];                    // CSR row starts
__device__ int   g_woff[NN];                        // scatter cursors
__device__ int   g_csrc[EE];                        // CSR src node ids

__device__ __forceinline__ float lrelu(float v) { return v > 0.f ? v : NEG * v; }

// ---------------- CSR build --------------------------------------------------
__global__ void k_zero_cnt() {
    int i = blockIdx.x * blockDim.x + threadIdx.x;
    if (i < NN) g_cnt[i] = 0;
}

__global__ void k_hist(const int* __restrict__ dst) {
    int i = blockIdx.x * blockDim.x + threadIdx.x;
    if (i >= EE / 4) return;
    const int4 d = ((const int4*)dst)[i];
    atomicAdd(&g_cnt[d.x], 1);
    atomicAdd(&g_cnt[d.y], 1);
    atomicAdd(&g_cnt[d.z], 1);
    atomicAdd(&g_cnt[d.w], 1);
}

__global__ void k_scan() {
    __shared__ int part[1024];
    const int t = threadIdx.x;
    const int CH = 40;
    const int base = t * CH;
    int s = 0;
#pragma unroll 8
    for (int i = 0; i < CH; i++) {
        int idx = base + i;
        if (idx < NN) s += g_cnt[idx];
    }
    part[t] = s;
    __syncthreads();
    for (int o = 1; o < 1024; o <<= 1) {
        int v = (t >= o) ? part[t - o] : 0;
        __syncthreads();
        part[t] += v;
        __syncthreads();
    }
    int excl = (t == 0) ? 0 : part[t - 1];
    for (int i = 0; i < CH; i++) {
        int idx = base + i;
        if (idx < NN) {
            g_rs[idx]   = excl;
            g_woff[idx] = excl;
            excl += g_cnt[idx];
        }
    }
    if (t == 1023) g_rs[NN] = part[1023];
}

__global__ void k_scatter(const int* __restrict__ src, const int* __restrict__ dst) {
    int i = blockIdx.x * blockDim.x + threadIdx.x;
    if (i >= EE / 4) return;
    const int4 d = ((const int4*)dst)[i];
    const int4 s = ((const int4*)src)[i];
    g_csrc[atomicAdd(&g_woff[d.x], 1)] = s.x;
    g_csrc[atomicAdd(&g_woff[d.y], 1)] = s.y;
    g_csrc[atomicAdd(&g_woff[d.z], 1)] = s.z;
    g_csrc[atomicAdd(&g_woff[d.w], 1)] = s.w;
}

// ---------------- K1: h = x @ W  (SIMT, pipelined, conflict-tuned) ----------
// 128x128 block tile, 8x8 thread tile; thread cols = {tx*4..+3, 64+tx*4..+3}
// so B-fragment LDS.128s hit the 2-phase minimum. Loop order per chunk:
// sync -> STS(prefetched) -> sync -> LDG(next) -> compute  (LDG hidden).
__global__ __launch_bounds__(256) void k_gemm(const float* __restrict__ x_in,
                                              int layer,
                                              const float* __restrict__ W,
                                              const float* __restrict__ as_w,
                                              const float* __restrict__ ad_w) {
    const float* x = (layer == 0) ? x_in : g_x;
    __shared__ float As[8][FD];   // [k][row]
    __shared__ float Bs[8][FD];   // [k][col]
    const int tid  = threadIdx.x;
    const int tx   = tid & 15;          // col group
    const int ty   = tid >> 4;          // row group (8 rows)
    const int row0 = blockIdx.x * 128;

    const int lrow = tid >> 1;          // x loader
    const int lk4  = (tid & 1) * 4;
    const int wk   = tid >> 5;          // W loader
    const int wc   = (tid & 31) * 4;
    const int grow = min(row0 + lrow, NN - 1);

    float acc[8][8];
#pragma unroll
    for (int i = 0; i < 8; i++)
#pragma unroll
        for (int j = 0; j < 8; j++) acc[i][j] = 0.f;

    // preload chunk 0
    float4 va = *(const float4*)&x[grow * FD + lk4];
    float4 vb = *(const float4*)&W[wk * FD + wc];

    for (int c = 0; c < 16; c++) {
        __syncthreads();                 // everyone done reading previous chunk
        As[lk4 + 0][lrow] = va.x; As[lk4 + 1][lrow] = va.y;
        As[lk4 + 2][lrow] = va.z; As[lk4 + 3][lrow] = va.w;
        *(float4*)&Bs[wk][wc] = vb;
        __syncthreads();
        if (c < 15) {                    // issue next LDG, hidden under compute
            va = *(const float4*)&x[grow * FD + (c + 1) * 8 + lk4];
            vb = *(const float4*)&W[((c + 1) * 8 + wk) * FD + wc];
        }
#pragma unroll
        for (int kk = 0; kk < 8; kk++) {
            float a[8], b[8];
            *(float4*)&a[0] = *(const float4*)&As[kk][ty * 8];
            *(float4*)&a[4] = *(const float4*)&As[kk][ty * 8 + 4];
            *(float4*)&b[0] = *(const float4*)&Bs[kk][tx * 4];
            *(float4*)&b[4] = *(const float4*)&Bs[kk][64 + tx * 4];
#pragma unroll
            for (int i = 0; i < 8; i++)
#pragma unroll
                for (int j = 0; j < 8; j++) acc[i][j] += a[i] * b[j];
        }
    }

    // ---- epilogue: bf16 h rows (two col groups) ----
#pragma unroll
    for (int i = 0; i < 8; i++) {
        const int r = row0 + ty * 8 + i;
        if (r < NN) {
            __nv_bfloat162 p0 = __floats2bfloat162_rn(acc[i][0], acc[i][1]);
            __nv_bfloat162 p1 = __floats2bfloat162_rn(acc[i][2], acc[i][3]);
            uint2 pk; pk.x = *(unsigned int*)&p0; pk.y = *(unsigned int*)&p1;
            *(uint2*)&g_hb[r * FD + tx * 4] = pk;
            __nv_bfloat162 q0 = __floats2bfloat162_rn(acc[i][4], acc[i][5]);
            __nv_bfloat162 q1 = __floats2bfloat162_rn(acc[i][6], acc[i][7]);
            uint2 qk; qk.x = *(unsigned int*)&q0; qk.y = *(unsigned int*)&q1;
            *(uint2*)&g_hb[r * FD + 64 + tx * 4] = qk;
        }
    }

    // ---- fused attention logits ----
    // group1 cols tx*4..+3 -> head (tx>>3); group2 cols 64+tx*4..+3 -> head 2+(tx>>3)
    float aw1[4], dw1[4], aw2[4], dw2[4];
#pragma unroll
    for (int j = 0; j < 4; j++) {
        aw1[j] = as_w[tx * 4 + j];      dw1[j] = ad_w[tx * 4 + j];
        aw2[j] = as_w[64 + tx * 4 + j]; dw2[j] = ad_w[64 + tx * 4 + j];
    }
    const int h1 = tx >> 3, h2 = 2 + (tx >> 3);
#pragma unroll
    for (int i = 0; i < 8; i++) {
        float s1 = 0.f, d1 = 0.f, s2 = 0.f, d2 = 0.f;
#pragma unroll
        for (int j = 0; j < 4; j++) {
            s1 += acc[i][j] * aw1[j];     d1 += acc[i][j] * dw1[j];
            s2 += acc[i][4 + j] * aw2[j]; d2 += acc[i][4 + j] * dw2[j];
        }
        // reduce over the 8 lanes sharing this (row, head) — tx%8 groups are
        // lane-aligned (lane = (ty&1)*16 + tx)
#pragma unroll
        for (int o = 1; o < 8; o <<= 1) {
            s1 += __shfl_xor_sync(0xffffffffu, s1, o);
            d1 += __shfl_xor_sync(0xffffffffu, d1, o);
            s2 += __shfl_xor_sync(0xffffffffu, s2, o);
            d2 += __shfl_xor_sync(0xffffffffu, d2, o);
        }
        const int r = row0 + ty * 8 + i;
        if ((tx & 7) == 0 && r < NN) {
            g_as[r * HH + h1] = s1; g_ad[r * HH + h1] = d1;
            g_as[r * HH + h2] = s2; g_ad[r * HH + h2] = d2;
        }
    }
}

// ---------------- K2: single-pass attention + aggregation + epilogue --------
__global__ __launch_bounds__(256) void k_attn(int last,
                           const float* __restrict__ bias,
                           const float* __restrict__ gamma,
                           const float* __restrict__ beta,
                           const float* __restrict__ mean,
                           const float* __restrict__ var,
                           const float* __restrict__ w_out,
                           const float* __restrict__ b_out,
                           float* __restrict__ out) {
    __shared__ float sw[8][32 * 4];
    __shared__ int   ssrc[8][32];
    const int n    = (blockIdx.x * blockDim.x + threadIdx.x) >> 5;
    const int wid  = threadIdx.x >> 5;
    const int lane = threadIdx.x & 31;
    if (n >= NN) return;
    const int rs = g_rs[n], re = g_rs[n + 1];
    const int head = lane >> 3;

    const float4 adv = *(const float4*)&g_ad[n * HH];
    const float4 asn = *(const float4*)&g_as[n * HH];

    const float ws0 = __expf(lrelu(asn.x + adv.x));
    const float ws1 = __expf(lrelu(asn.y + adv.y));
    const float ws2 = __expf(lrelu(asn.z + adv.z));
    const float ws3 = __expf(lrelu(asn.w + adv.w));
    const float w_self = (head == 0) ? ws0 : (head == 1) ? ws1 : (head == 2) ? ws2 : ws3;

    float4 acc;
    {
        const uint2 hv = *(const uint2*)&g_hb[n * FD + lane * 4];
        const float2 f0 = __bfloat1622float2(*(const __nv_bfloat162*)&hv.x);
        const float2 f1 = __bfloat1622float2(*(const __nv_bfloat162*)&hv.y);
        acc.x = f0.x * w_self; acc.y = f0.y * w_self;
        acc.z = f1.x * w_self; acc.w = f1.y * w_self;
    }

    float p0 = 0.f, p1 = 0.f, p2 = 0.f, p3 = 0.f;

    for (int base = rs; base < re; base += 32) {
        const int j = base + lane;
        float4 w = make_float4(0.f, 0.f, 0.f, 0.f);
        int sreg = 0;
        if (j < re) {
            sreg = g_csrc[j];
            const float4 as = *(const float4*)&g_as[sreg * HH];
            w.x = __expf(lrelu(as.x + adv.x));
            w.y = __expf(lrelu(as.y + adv.y));
            w.z = __expf(lrelu(as.z + adv.z));
            w.w = __expf(lrelu(as.w + adv.w));
            p0 += w.x; p1 += w.y; p2 += w.z; p3 += w.w;
        }
        __syncwarp();
        *(float4*)&sw[wid][lane * 4] = w;
        ssrc[wid][lane] = sreg;
        __syncwarp();
        const int cnt = min(32, re - base);
        int jj = 0;
        for (; jj + 4 <= cnt; jj += 4) {
            const int s0 = ssrc[wid][jj + 0];
            const int s1 = ssrc[wid][jj + 1];
            const int s2 = ssrc[wid][jj + 2];
            const int s3 = ssrc[wid][jj + 3];
            const float w0 = sw[wid][(jj + 0) * 4 + head];
            const float w1 = sw[wid][(jj + 1) * 4 + head];
            const float w2 = sw[wid][(jj + 2) * 4 + head];
            const float w3 = sw[wid][(jj + 3) * 4 + head];
            const uint2 v0 = *(const uint2*)&g_hb[s0 * FD + lane * 4];
            const uint2 v1 = *(const uint2*)&g_hb[s1 * FD + lane * 4];
            const uint2 v2 = *(const uint2*)&g_hb[s2 * FD + lane * 4];
            const uint2 v3 = *(const uint2*)&g_hb[s3 * FD + lane * 4];
            float2 a0 = __bfloat1622float2(*(const __nv_bfloat162*)&v0.x);
            float2 b0 = __bfloat1622float2(*(const __nv_bfloat162*)&v0.y);
            acc.x += a0.x * w0; acc.y += a0.y * w0; acc.z += b0.x * w0; acc.w += b0.y * w0;
            float2 a1 = __bfloat1622float2(*(const __nv_bfloat162*)&v1.x);
            float2 b1 = __bfloat1622float2(*(const __nv_bfloat162*)&v1.y);
            acc.x += a1.x * w1; acc.y += a1.y * w1; acc.z += b1.x * w1; acc.w += b1.y * w1;
            float2 a2 = __bfloat1622float2(*(const __nv_bfloat162*)&v2.x);
            float2 b2 = __bfloat1622float2(*(const __nv_bfloat162*)&v2.y);
            acc.x += a2.x * w2; acc.y += a2.y * w2; acc.z += b2.x * w2; acc.w += b2.y * w2;
            float2 a3 = __bfloat1622float2(*(const __nv_bfloat162*)&v3.x);
            float2 b3 = __bfloat1622float2(*(const __nv_bfloat162*)&v3.y);
            acc.x += a3.x * w3; acc.y += a3.y * w3; acc.z += b3.x * w3; acc.w += b3.y * w3;
        }
        for (; jj < cnt; jj++) {
            const int   s  = ssrc[wid][jj];
            const float ww = sw[wid][jj * 4 + head];
            const uint2 v  = *(const uint2*)&g_hb[s * FD + lane * 4];
            float2 a = __bfloat1622float2(*(const __nv_bfloat162*)&v.x);
            float2 b = __bfloat1622float2(*(const __nv_bfloat162*)&v.y);
            acc.x += a.x * ww; acc.y += a.y * ww;
            acc.z += b.x * ww; acc.w += b.y * ww;
        }
    }

#pragma unroll
    for (int o = 16; o > 0; o >>= 1) {
        p0 += __shfl_xor_sync(0xffffffffu, p0, o);
        p1 += __shfl_xor_sync(0xffffffffu, p1, o);
        p2 += __shfl_xor_sync(0xffffffffu, p2, o);
        p3 += __shfl_xor_sync(0xffffffffu, p3, o);
    }
    const float denom = ((head == 0) ? p0 : (head == 1) ? p1 : (head == 2) ? p2 : p3)
                        + w_self;
    const float inv = 1.f / (denom + 1e-16f);
    acc.x *= inv; acc.y *= inv; acc.z *= inv; acc.w *= inv;

    const int c4 = lane * 4;
    const float4 b  = *(const float4*)&bias[c4];
    const float4 g  = *(const float4*)&gamma[c4];
    const float4 bt = *(const float4*)&beta[c4];
    const float4 mm = *(const float4*)&mean[c4];
    const float4 vr = *(const float4*)&var[c4];
    float4 o;
    o.x = fmaxf((acc.x + b.x - mm.x) * rsqrtf(vr.x + BNEPS) * g.x + bt.x, 0.f);
    o.y = fmaxf((acc.y + b.y - mm.y) * rsqrtf(vr.y + BNEPS) * g.y + bt.y, 0.f);
    o.z = fmaxf((acc.z + b.z - mm.z) * rsqrtf(vr.z + BNEPS) * g.z + bt.z, 0.f);
    o.w = fmaxf((acc.w + b.w - mm.w) * rsqrtf(vr.w + BNEPS) * g.w + bt.w, 0.f);

    if (!last) {
        *(float4*)&g_x[n * FD + c4] = o;
    } else {
        const float4 wv = *(const float4*)&w_out[c4];
        float sum = o.x * wv.x + o.y * wv.y + o.z * wv.z + o.w * wv.w;
#pragma unroll
        for (int off = 16; off > 0; off >>= 1)
            sum += __shfl_down_sync(0xffffffffu, sum, off);
        if (lane == 0) out[n] = sum + b_out[0];
    }
}

// ---------------- launcher ---------------------------------------------------
extern "C" void kernel_launch(void* const* d_in, const int* in_sizes, int n_in,
                              void* d_out, int out_size) {
    const float* x       = (const float*)d_in[0];
    const int*   ei      = (const int*)  d_in[1];
    const float* W       = (const float*)d_in[2];
    const float* att_src = (const float*)d_in[3];
    const float* att_dst = (const float*)d_in[4];
    const float* bias    = (const float*)d_in[5];
    const float* gamma   = (const float*)d_in[6];
    const float* beta    = (const float*)d_in[7];
    const float* mean    = (const float*)d_in[8];
    const float* var     = (const float*)d_in[9];
    const float* w_out   = (const float*)d_in[10];
    const float* b_out   = (const float*)d_in[11];

    const int* src = ei;
    const int* dst = ei + EE;

    const int WGRID = (NN * 32 + 255) / 256;
    const int GGRID = (NN + 127) / 128;

    k_zero_cnt<<<(NN + 255) / 256, 256>>>();
    k_hist    <<<(EE / 4 + 255) / 256, 256>>>(dst);
    k_scan    <<<1, 1024>>>();
    k_gemm    <<<GGRID, 256>>>(x, 0, W, att_src, att_dst);        // sampled launch
    k_scatter <<<(EE / 4 + 255) / 256, 256>>>(src, dst);

    for (int l = 0; l < LL; l++) {
        if (l > 0)
            k_gemm<<<GGRID, 256>>>(x, l, W + l * FD * FD,
                                   att_src + l * FD, att_dst + l * FD);
        k_attn<<<WGRID, 256>>>(l == LL - 1,
                               bias + l * FD, gamma + l * FD, beta + l * FD,
                               mean + l * FD, var + l * FD,
                               w_out, b_out, (float*)d_out);
    }
}

// round 8
// speedup vs baseline: 1.2867x; 1.0187x over previous
#include <cuda_runtime.h>
#include <cuda_bf16.h>

#define NN 40000
#define EE 640000
#define FD 128
#define HH 4
#define LL 3
#define NEG 0.2f
#define BNEPS 1e-5f

// ---------------- scratch (device globals; no allocations allowed) ----------
__device__ __align__(16) __nv_bfloat16 g_hb[NN * FD];  // h rows in bf16 [N,128]
__device__ __align__(16) float g_x  [NN * FD];     // layer input ping    [N,128]
__device__ __align__(16) float g_as [NN * HH];     // per-head src logits [N,4]
__device__ __align__(16) float g_ad [NN * HH];     // per-head dst logits [N,4]
__device__ int   g_cnt [NN];                        // in-degree counts
__device__ int   g_rs  [NN + 1];                    // CSR row starts
__device__ int   g_woff[NN];                        // scatter cursors
__device__ int   g_csrc[EE];                        // CSR src node ids

__device__ __forceinline__ float lrelu(float v) { return v > 0.f ? v : NEG * v; }

// ---------------- CSR build --------------------------------------------------
__global__ void k_zero_cnt() {
    int i = blockIdx.x * blockDim.x + threadIdx.x;
    if (i < NN) g_cnt[i] = 0;
}

__global__ void k_hist(const int* __restrict__ dst) {
    int i = blockIdx.x * blockDim.x + threadIdx.x;
    if (i >= EE / 4) return;
    const int4 d = ((const int4*)dst)[i];
    atomicAdd(&g_cnt[d.x], 1);
    atomicAdd(&g_cnt[d.y], 1);
    atomicAdd(&g_cnt[d.z], 1);
    atomicAdd(&g_cnt[d.w], 1);
}

__global__ void k_scan() {
    __shared__ int part[1024];
    const int t = threadIdx.x;
    const int CH = 40;
    const int base = t * CH;
    int s = 0;
#pragma unroll 8
    for (int i = 0; i < CH; i++) {
        int idx = base + i;
        if (idx < NN) s += g_cnt[idx];
    }
    part[t] = s;
    __syncthreads();
    for (int o = 1; o < 1024; o <<= 1) {
        int v = (t >= o) ? part[t - o] : 0;
        __syncthreads();
        part[t] += v;
        __syncthreads();
    }
    int excl = (t == 0) ? 0 : part[t - 1];
    for (int i = 0; i < CH; i++) {
        int idx = base + i;
        if (idx < NN) {
            g_rs[idx]   = excl;
            g_woff[idx] = excl;
            excl += g_cnt[idx];
        }
    }
    if (t == 1023) g_rs[NN] = part[1023];
}

__global__ void k_scatter(const int* __restrict__ src, const int* __restrict__ dst) {
    int i = blockIdx.x * blockDim.x + threadIdx.x;
    if (i >= EE / 4) return;
    const int4 d = ((const int4*)dst)[i];
    const int4 s = ((const int4*)src)[i];
    g_csrc[atomicAdd(&g_woff[d.x], 1)] = s.x;
    g_csrc[atomicAdd(&g_woff[d.y], 1)] = s.y;
    g_csrc[atomicAdd(&g_woff[d.z], 1)] = s.z;
    g_csrc[atomicAdd(&g_woff[d.w], 1)] = s.w;
}

// ---------------- K1: h = x @ W  (SIMT, double-buffered, 1 sync/chunk) ------
// 128x128 block tile, 8x8 thread tile, K chunk = 16, 2-stage smem.
// Per chunk: LDG(c+1) -> compute(c) -> STS(c+1) -> sync.
__global__ __launch_bounds__(256) void k_gemm(const float* __restrict__ x_in,
                                              int layer,
                                              const float* __restrict__ W,
                                              const float* __restrict__ as_w,
                                              const float* __restrict__ ad_w) {
    const float* x = (layer == 0) ? x_in : g_x;
    __shared__ float As[2][16][FD];   // [buf][k][row]
    __shared__ float Bs[2][16][FD];   // [buf][k][col]
    const int tid  = threadIdx.x;
    const int tx   = tid & 15;
    const int ty   = tid >> 4;
    const int row0 = blockIdx.x * 128;

    const int arow = tid >> 1;            // A loader: row, 8 k's
    const int ak   = (tid & 1) * 8;
    const int bk   = tid >> 4;            // B loader: k row 0..15
    const int bc   = (tid & 15) * 8;      // 8 cols
    const int grow = min(row0 + arow, NN - 1);

    float acc[8][8];
#pragma unroll
    for (int i = 0; i < 8; i++)
#pragma unroll
        for (int j = 0; j < 8; j++) acc[i][j] = 0.f;

    // chunk 0: load + store buf 0
    float4 va0 = *(const float4*)&x[grow * FD + ak];
    float4 va1 = *(const float4*)&x[grow * FD + ak + 4];
    float4 vb0 = *(const float4*)&W[bk * FD + bc];
    float4 vb1 = *(const float4*)&W[bk * FD + bc + 4];
    As[0][ak + 0][arow] = va0.x; As[0][ak + 1][arow] = va0.y;
    As[0][ak + 2][arow] = va0.z; As[0][ak + 3][arow] = va0.w;
    As[0][ak + 4][arow] = va1.x; As[0][ak + 5][arow] = va1.y;
    As[0][ak + 6][arow] = va1.z; As[0][ak + 7][arow] = va1.w;
    *(float4*)&Bs[0][bk][bc]     = vb0;
    *(float4*)&Bs[0][bk][bc + 4] = vb1;
    __syncthreads();

#pragma unroll 2
    for (int c = 0; c < 8; c++) {
        const int buf = c & 1;
        if (c < 7) {                      // LDG next chunk (hidden under compute)
            const int kb = (c + 1) * 16;
            va0 = *(const float4*)&x[grow * FD + kb + ak];
            va1 = *(const float4*)&x[grow * FD + kb + ak + 4];
            vb0 = *(const float4*)&W[(kb + bk) * FD + bc];
            vb1 = *(const float4*)&W[(kb + bk) * FD + bc + 4];
        }
#pragma unroll
        for (int kk = 0; kk < 16; kk++) {
            float a[8], b[8];
            *(float4*)&a[0] = *(const float4*)&As[buf][kk][ty * 8];
            *(float4*)&a[4] = *(const float4*)&As[buf][kk][ty * 8 + 4];
            *(float4*)&b[0] = *(const float4*)&Bs[buf][kk][tx * 4];
            *(float4*)&b[4] = *(const float4*)&Bs[buf][kk][64 + tx * 4];
#pragma unroll
            for (int i = 0; i < 8; i++)
#pragma unroll
                for (int j = 0; j < 8; j++) acc[i][j] += a[i] * b[j];
        }
        if (c < 7) {                      // STS next chunk (data arrived)
            const int nb = buf ^ 1;
            As[nb][ak + 0][arow] = va0.x; As[nb][ak + 1][arow] = va0.y;
            As[nb][ak + 2][arow] = va0.z; As[nb][ak + 3][arow] = va0.w;
            As[nb][ak + 4][arow] = va1.x; As[nb][ak + 5][arow] = va1.y;
            As[nb][ak + 6][arow] = va1.z; As[nb][ak + 7][arow] = va1.w;
            *(float4*)&Bs[nb][bk][bc]     = vb0;
            *(float4*)&Bs[nb][bk][bc + 4] = vb1;
            __syncthreads();
        }
    }

    // ---- epilogue: bf16 h rows (two col groups: tx*4 and 64+tx*4) ----
#pragma unroll
    for (int i = 0; i < 8; i++) {
        const int r = row0 + ty * 8 + i;
        if (r < NN) {
            __nv_bfloat162 p0 = __floats2bfloat162_rn(acc[i][0], acc[i][1]);
            __nv_bfloat162 p1 = __floats2bfloat162_rn(acc[i][2], acc[i][3]);
            uint2 pk; pk.x = *(unsigned int*)&p0; pk.y = *(unsigned int*)&p1;
            *(uint2*)&g_hb[r * FD + tx * 4] = pk;
            __nv_bfloat162 q0 = __floats2bfloat162_rn(acc[i][4], acc[i][5]);
            __nv_bfloat162 q1 = __floats2bfloat162_rn(acc[i][6], acc[i][7]);
            uint2 qk; qk.x = *(unsigned int*)&q0; qk.y = *(unsigned int*)&q1;
            *(uint2*)&g_hb[r * FD + 64 + tx * 4] = qk;
        }
    }

    // ---- fused attention logits ----
    float aw1[4], dw1[4], aw2[4], dw2[4];
#pragma unroll
    for (int j = 0; j < 4; j++) {
        aw1[j] = as_w[tx * 4 + j];      dw1[j] = ad_w[tx * 4 + j];
        aw2[j] = as_w[64 + tx * 4 + j]; dw2[j] = ad_w[64 + tx * 4 + j];
    }
    const int h1 = tx >> 3, h2 = 2 + (tx >> 3);
#pragma unroll
    for (int i = 0; i < 8; i++) {
        float s1 = 0.f, d1 = 0.f, s2 = 0.f, d2 = 0.f;
#pragma unroll
        for (int j = 0; j < 4; j++) {
            s1 += acc[i][j] * aw1[j];     d1 += acc[i][j] * dw1[j];
            s2 += acc[i][4 + j] * aw2[j]; d2 += acc[i][4 + j] * dw2[j];
        }
#pragma unroll
        for (int o = 1; o < 8; o <<= 1) {
            s1 += __shfl_xor_sync(0xffffffffu, s1, o);
            d1 += __shfl_xor_sync(0xffffffffu, d1, o);
            s2 += __shfl_xor_sync(0xffffffffu, s2, o);
            d2 += __shfl_xor_sync(0xffffffffu, d2, o);
        }
        const int r = row0 + ty * 8 + i;
        if ((tx & 7) == 0 && r < NN) {
            g_as[r * HH + h1] = s1; g_ad[r * HH + h1] = d1;
            g_as[r * HH + h2] = s2; g_ad[r * HH + h2] = d2;
        }
    }
}

// ---------------- K2: single-pass attention + aggregation + epilogue --------
__global__ __launch_bounds__(256) void k_attn(int last,
                           const float* __restrict__ bias,
                           const float* __restrict__ gamma,
                           const float* __restrict__ beta,
                           const float* __restrict__ mean,
                           const float* __restrict__ var,
                           const float* __restrict__ w_out,
                           const float* __restrict__ b_out,
                           float* __restrict__ out) {
    __shared__ float sw[8][32 * 4];
    __shared__ int   ssrc[8][32];
    const int n    = (blockIdx.x * blockDim.x + threadIdx.x) >> 5;
    const int wid  = threadIdx.x >> 5;
    const int lane = threadIdx.x & 31;
    if (n >= NN) return;
    const int rs = g_rs[n], re = g_rs[n + 1];
    const int head = lane >> 3;

    const float4 adv = *(const float4*)&g_ad[n * HH];
    const float4 asn = *(const float4*)&g_as[n * HH];

    const float ws0 = __expf(lrelu(asn.x + adv.x));
    const float ws1 = __expf(lrelu(asn.y + adv.y));
    const float ws2 = __expf(lrelu(asn.z + adv.z));
    const float ws3 = __expf(lrelu(asn.w + adv.w));
    const float w_self = (head == 0) ? ws0 : (head == 1) ? ws1 : (head == 2) ? ws2 : ws3;

    float4 acc;
    {
        const uint2 hv = *(const uint2*)&g_hb[n * FD + lane * 4];
        const float2 f0 = __bfloat1622float2(*(const __nv_bfloat162*)&hv.x);
        const float2 f1 = __bfloat1622float2(*(const __nv_bfloat162*)&hv.y);
        acc.x = f0.x * w_self; acc.y = f0.y * w_self;
        acc.z = f1.x * w_self; acc.w = f1.y * w_self;
    }

    float p0 = 0.f, p1 = 0.f, p2 = 0.f, p3 = 0.f;

    for (int base = rs; base < re; base += 32) {
        const int j = base + lane;
        float4 w = make_float4(0.f, 0.f, 0.f, 0.f);
        int sreg = 0;
        if (j < re) {
            sreg = g_csrc[j];
            const float4 as = *(const float4*)&g_as[sreg * HH];
            w.x = __expf(lrelu(as.x + adv.x));
            w.y = __expf(lrelu(as.y + adv.y));
            w.z = __expf(lrelu(as.z + adv.z));
            w.w = __expf(lrelu(as.w + adv.w));
            p0 += w.x; p1 += w.y; p2 += w.z; p3 += w.w;
        }
        __syncwarp();
        *(float4*)&sw[wid][lane * 4] = w;
        ssrc[wid][lane] = sreg;
        __syncwarp();
        const int cnt = min(32, re - base);
        int jj = 0;
        for (; jj + 4 <= cnt; jj += 4) {
            const int s0 = ssrc[wid][jj + 0];
            const int s1 = ssrc[wid][jj + 1];
            const int s2 = ssrc[wid][jj + 2];
            const int s3 = ssrc[wid][jj + 3];
            const float w0 = sw[wid][(jj + 0) * 4 + head];
            const float w1 = sw[wid][(jj + 1) * 4 + head];
            const float w2 = sw[wid][(jj + 2) * 4 + head];
            const float w3 = sw[wid][(jj + 3) * 4 + head];
            const uint2 v0 = *(const uint2*)&g_hb[s0 * FD + lane * 4];
            const uint2 v1 = *(const uint2*)&g_hb[s1 * FD + lane * 4];
            const uint2 v2 = *(const uint2*)&g_hb[s2 * FD + lane * 4];
            const uint2 v3 = *(const uint2*)&g_hb[s3 * FD + lane * 4];
            float2 a0 = __bfloat1622float2(*(const __nv_bfloat162*)&v0.x);
            float2 b0 = __bfloat1622float2(*(const __nv_bfloat162*)&v0.y);
            acc.x += a0.x * w0; acc.y += a0.y * w0; acc.z += b0.x * w0; acc.w += b0.y * w0;
            float2 a1 = __bfloat1622float2(*(const __nv_bfloat162*)&v1.x);
            float2 b1 = __bfloat1622float2(*(const __nv_bfloat162*)&v1.y);
            acc.x += a1.x * w1; acc.y += a1.y * w1; acc.z += b1.x * w1; acc.w += b1.y * w1;
            float2 a2 = __bfloat1622float2(*(const __nv_bfloat162*)&v2.x);
            float2 b2 = __bfloat1622float2(*(const __nv_bfloat162*)&v2.y);
            acc.x += a2.x * w2; acc.y += a2.y * w2; acc.z += b2.x * w2; acc.w += b2.y * w2;
            float2 a3 = __bfloat1622float2(*(const __nv_bfloat162*)&v3.x);
            float2 b3 = __bfloat1622float2(*(const __nv_bfloat162*)&v3.y);
            acc.x += a3.x * w3; acc.y += a3.y * w3; acc.z += b3.x * w3; acc.w += b3.y * w3;
        }
        for (; jj < cnt; jj++) {
            const int   s  = ssrc[wid][jj];
            const float ww = sw[wid][jj * 4 + head];
            const uint2 v  = *(const uint2*)&g_hb[s * FD + lane * 4];
            float2 a = __bfloat1622float2(*(const __nv_bfloat162*)&v.x);
            float2 b = __bfloat1622float2(*(const __nv_bfloat162*)&v.y);
            acc.x += a.x * ww; acc.y += a.y * ww;
            acc.z += b.x * ww; acc.w += b.y * ww;
        }
    }

#pragma unroll
    for (int o = 16; o > 0; o >>= 1) {
        p0 += __shfl_xor_sync(0xffffffffu, p0, o);
        p1 += __shfl_xor_sync(0xffffffffu, p1, o);
        p2 += __shfl_xor_sync(0xffffffffu, p2, o);
        p3 += __shfl_xor_sync(0xffffffffu, p3, o);
    }
    const float denom = ((head == 0) ? p0 : (head == 1) ? p1 : (head == 2) ? p2 : p3)
                        + w_self;
    const float inv = 1.f / (denom + 1e-16f);
    acc.x *= inv; acc.y *= inv; acc.z *= inv; acc.w *= inv;

    const int c4 = lane * 4;
    const float4 b  = *(const float4*)&bias[c4];
    const float4 g  = *(const float4*)&gamma[c4];
    const float4 bt = *(const float4*)&beta[c4];
    const float4 mm = *(const float4*)&mean[c4];
    const float4 vr = *(const float4*)&var[c4];
    float4 o;
    o.x = fmaxf((acc.x + b.x - mm.x) * rsqrtf(vr.x + BNEPS) * g.x + bt.x, 0.f);
    o.y = fmaxf((acc.y + b.y - mm.y) * rsqrtf(vr.y + BNEPS) * g.y + bt.y, 0.f);
    o.z = fmaxf((acc.z + b.z - mm.z) * rsqrtf(vr.z + BNEPS) * g.z + bt.z, 0.f);
    o.w = fmaxf((acc.w + b.w - mm.w) * rsqrtf(vr.w + BNEPS) * g.w + bt.w, 0.f);

    if (!last) {
        *(float4*)&g_x[n * FD + c4] = o;
    } else {
        const float4 wv = *(const float4*)&w_out[c4];
        float sum = o.x * wv.x + o.y * wv.y + o.z * wv.z + o.w * wv.w;
#pragma unroll
        for (int off = 16; off > 0; off >>= 1)
            sum += __shfl_down_sync(0xffffffffu, sum, off);
        if (lane == 0) out[n] = sum + b_out[0];
    }
}

// ---------------- launcher ---------------------------------------------------
// CSR build forked onto a side stream, overlapped with layer-0 GEMM.
// Stream/event handles are created once, on the first (uncaptured) call;
// the per-call launch sequence and GPU work are identical every call.
extern "C" void kernel_launch(void* const* d_in, const int* in_sizes, int n_in,
                              void* d_out, int out_size) {
    static cudaStream_t s2 = nullptr;
    static cudaEvent_t  evf = nullptr, evj = nullptr;
    if (s2 == nullptr) {
        cudaStreamCreateWithFlags(&s2, cudaStreamNonBlocking);
        cudaEventCreateWithFlags(&evf, cudaEventDisableTiming);
        cudaEventCreateWithFlags(&evj, cudaEventDisableTiming);
    }

    const float* x       = (const float*)d_in[0];
    const int*   ei      = (const int*)  d_in[1];
    const float* W       = (const float*)d_in[2];
    const float* att_src = (const float*)d_in[3];
    const float* att_dst = (const float*)d_in[4];
    const float* bias    = (const float*)d_in[5];
    const float* gamma   = (const float*)d_in[6];
    const float* beta    = (const float*)d_in[7];
    const float* mean    = (const float*)d_in[8];
    const float* var     = (const float*)d_in[9];
    const float* w_out   = (const float*)d_in[10];
    const float* b_out   = (const float*)d_in[11];

    const int* src = ei;
    const int* dst = ei + EE;

    const int WGRID = (NN * 32 + 255) / 256;
    const int GGRID = (NN + 127) / 128;

    // fork: CSR chain on s2, concurrent with layer-0 GEMM on the main stream
    cudaEventRecord(evf, 0);
    cudaStreamWaitEvent(s2, evf, 0);
    k_zero_cnt<<<(NN + 255) / 256, 256, 0, s2>>>();
    k_hist    <<<(EE / 4 + 255) / 256, 256, 0, s2>>>(dst);
    k_scan    <<<1, 1024, 0, s2>>>();
    k_scatter <<<(EE / 4 + 255) / 256, 256, 0, s2>>>(src, dst);
    cudaEventRecord(evj, s2);

    k_gemm<<<GGRID, 256>>>(x, 0, W, att_src, att_dst);

    // join: attention needs both CSR and GEMM results
    cudaStreamWaitEvent(0, evj, 0);

    for (int l = 0; l < LL; l++) {
        if (l > 0)
            k_gemm<<<GGRID, 256>>>(x, l, W + l * FD * FD,
                                   att_src + l * FD, att_dst + l * FD);
        k_attn<<<WGRID, 256>>>(l == LL - 1,
                               bias + l * FD, gamma + l * FD, beta + l * FD,
                               mean + l * FD, var + l * FD,
                               w_out, b_out, (float*)d_out);
    }
}

// round 10
// speedup vs baseline: 1.4290x; 1.1106x over previous
#include <cuda_runtime.h>
#include <cuda_bf16.h>
#include <cstdint>

#define NN 40000
#define EE 640000
#define FD 128
#define HH 4
#define LL 3
#define NEG 0.2f
#define BNEPS 1e-5f

// ---------------- scratch (device globals; no allocations allowed) ----------
__device__ __align__(16) __nv_bfloat16 g_hb[NN * FD];   // h rows bf16 [N,128]
__device__ __align__(16) float g_x  [NN * FD];
__device__ __align__(16) float g_as [NN * HH];
__device__ __align__(16) float g_ad [NN * HH];
__device__ int   g_cnt [NN];
__device__ int   g_rs  [NN + 1];
__device__ int   g_woff[NN];
__device__ int   g_csrc[EE];
// W^T in blocked 8x8-matrix layout (128B per matrix), bf16 hi/lo, per layer
__device__ __align__(16) __nv_bfloat16 g_wbh[LL * FD * FD];
__device__ __align__(16) __nv_bfloat16 g_wbl[LL * FD * FD];

__device__ __forceinline__ float lrelu(float v) { return v > 0.f ? v : NEG * v; }

__device__ __forceinline__ uint32_t smem_u32(const void* p) {
    uint32_t a;
    asm("{ .reg .u64 t; cvta.to.shared.u64 t, %1; cvt.u32.u64 %0, t; }"
        : "=r"(a) : "l"(p));
    return a;
}

__device__ __forceinline__ void ldmx4(uint32_t& r0, uint32_t& r1,
                                      uint32_t& r2, uint32_t& r3, uint32_t addr) {
    asm volatile("ldmatrix.sync.aligned.m8n8.x4.shared.b16 {%0,%1,%2,%3}, [%4];"
                 : "=r"(r0), "=r"(r1), "=r"(r2), "=r"(r3) : "r"(addr));
}

__device__ __forceinline__ void mma_bf16(float c[4],
                                         uint32_t a0, uint32_t a1,
                                         uint32_t a2, uint32_t a3,
                                         uint32_t b0, uint32_t b1) {
    asm volatile("mma.sync.aligned.m16n8k16.row.col.f32.bf16.bf16.f32 "
                 "{%0,%1,%2,%3}, {%4,%5,%6,%7}, {%8,%9}, {%0,%1,%2,%3};"
                 : "+f"(c[0]), "+f"(c[1]), "+f"(c[2]), "+f"(c[3])
                 : "r"(a0), "r"(a1), "r"(a2), "r"(a3), "r"(b0), "r"(b1));
}

// ---------------- CSR build --------------------------------------------------
__global__ void k_zero_cnt() {
    int i = blockIdx.x * blockDim.x + threadIdx.x;
    if (i < NN) g_cnt[i] = 0;
}
__global__ void k_hist(const int* __restrict__ dst) {
    int i = blockIdx.x * blockDim.x + threadIdx.x;
    if (i >= EE / 4) return;
    const int4 d = ((const int4*)dst)[i];
    atomicAdd(&g_cnt[d.x], 1); atomicAdd(&g_cnt[d.y], 1);
    atomicAdd(&g_cnt[d.z], 1); atomicAdd(&g_cnt[d.w], 1);
}
__global__ void k_scan() {
    __shared__ int part[1024];
    const int t = threadIdx.x;
    const int CH = 40;
    const int base = t * CH;
    int s = 0;
#pragma unroll 8
    for (int i = 0; i < CH; i++) { int idx = base + i; if (idx < NN) s += g_cnt[idx]; }
    part[t] = s;
    __syncthreads();
    for (int o = 1; o < 1024; o <<= 1) {
        int v = (t >= o) ? part[t - o] : 0;
        __syncthreads();
        part[t] += v;
        __syncthreads();
    }
    int excl = (t == 0) ? 0 : part[t - 1];
    for (int i = 0; i < CH; i++) {
        int idx = base + i;
        if (idx < NN) { g_rs[idx] = excl; g_woff[idx] = excl; excl += g_cnt[idx]; }
    }
    if (t == 1023) g_rs[NN] = part[1023];
}
__global__ void k_scatter(const int* __restrict__ src, const int* __restrict__ dst) {
    int i = blockIdx.x * blockDim.x + threadIdx.x;
    if (i >= EE / 4) return;
    const int4 d = ((const int4*)dst)[i];
    const int4 s = ((const int4*)src)[i];
    g_csrc[atomicAdd(&g_woff[d.x], 1)] = s.x;
    g_csrc[atomicAdd(&g_woff[d.y], 1)] = s.y;
    g_csrc[atomicAdd(&g_woff[d.z], 1)] = s.z;
    g_csrc[atomicAdd(&g_woff[d.w], 1)] = s.w;
}

// ---------------- K0: W -> Bt blocked layout, bf16 hi/lo --------------------
// Bt[n][k] = W[k][n]; matrix (kblk, nblk) at ((kblk*16)+nblk)*128 bytes,
// inner offset (n&7)*16 + (k&7)*2.
__global__ void k_prep(const float* __restrict__ W) {
    int i = blockIdx.x * blockDim.x + threadIdx.x;
    if (i >= LL * FD * FD) return;
    const int l = i >> 14;
    const int k = (i >> 7) & 127;
    const int n = i & 127;
    const float v = W[i];
    const __nv_bfloat16 h  = __float2bfloat16(v);
    const __nv_bfloat16 lo = __float2bfloat16(v - __bfloat162float(h));
    const uint32_t off = (uint32_t)(((k >> 3) * 16 + (n >> 3)) * 128
                                    + (n & 7) * 16 + (k & 7) * 2);
    g_wbh[(l << 14) + (off >> 1)] = h;
    g_wbl[(l << 14) + (off >> 1)] = lo;
}

// ---------------- K1: h = x @ W via bf16 HMMA (3xbf16) + ldmatrix -----------
// 256 threads / 8 warps; block tile 128x128; warp tile m16 x n128.
// Smem: Ah(32K) Al(32K) Bh(32K) Bl(32K) in blocked 8x8-matrix layout.
__global__ __launch_bounds__(256) void k_gemm(const float* __restrict__ x_in,
                                              int layer,
                                              const float* __restrict__ as_w,
                                              const float* __restrict__ ad_w) {
    extern __shared__ __align__(16) unsigned char sm[];
    const float* x = (layer == 0) ? x_in : g_x;
    const int tid  = threadIdx.x;
    const int w    = tid >> 5;
    const int lane = tid & 31;
    const int row0 = blockIdx.x * 128;
    const uint32_t Ah = smem_u32(sm);

    // ---- copy pre-blocked B hi/lo tiles (32KB each) ----
    {
        const uint4* shp = (const uint4*)(g_wbh + (layer << 14));
        const uint4* slp = (const uint4*)(g_wbl + (layer << 14));
        uint4* dh = (uint4*)(sm + 65536);
        uint4* dl = (uint4*)(sm + 98304);
#pragma unroll
        for (int i = 0; i < 8; i++) {
            dh[tid + i * 256] = shp[tid + i * 256];
            dl[tid + i * 256] = slp[tid + i * 256];
        }
    }

    // ---- A: x rows -> bf16 hi/lo -> blocked smem ----
    {
        const int row   = tid >> 1;
        const int khalf = tid & 1;
        const int grow  = min(row0 + row, NN - 1);
        const float4* xr = (const float4*)&x[grow * FD + khalf * 64];
#pragma unroll
        for (int i = 0; i < 8; i++) {
            const float4 v0 = xr[i * 2];
            const float4 v1 = xr[i * 2 + 1];
            const float fv[8] = {v0.x, v0.y, v0.z, v0.w, v1.x, v1.y, v1.z, v1.w};
            uint32_t hi[4], lo[4];
#pragma unroll
            for (int j = 0; j < 4; j++) {
                const __nv_bfloat16 h0 = __float2bfloat16(fv[2 * j]);
                const __nv_bfloat16 h1 = __float2bfloat16(fv[2 * j + 1]);
                __nv_bfloat162 ph(h0, h1);
                hi[j] = *(uint32_t*)&ph;
                __nv_bfloat162 pl = __floats2bfloat162_rn(
                    fv[2 * j] - __bfloat162float(h0),
                    fv[2 * j + 1] - __bfloat162float(h1));
                lo[j] = *(uint32_t*)&pl;
            }
            const uint32_t off = (uint32_t)((((khalf * 8 + i) * 16 + (row >> 3)) * 128)
                                            + (row & 7) * 16);
            *(uint4*)(sm + off)         = *(uint4*)&hi[0];
            *(uint4*)(sm + 32768 + off) = *(uint4*)&lo[0];
        }
    }
    __syncthreads();

    // ---- compute: 8 k-steps, warp tile m16 x n128 ----
    float c[16][4];
#pragma unroll
    for (int i = 0; i < 16; i++)
#pragma unroll
        for (int j = 0; j < 4; j++) c[i][j] = 0.f;

    const int mo   = lane >> 3;          // ldmatrix quadrant
    const int kadd = mo >> 1;
    const int radd = mo & 1;
    const uint32_t inner = (uint32_t)((lane & 7) * 16);

#pragma unroll
    for (int s = 0; s < 8; s++) {
        uint32_t ah0, ah1, ah2, ah3, al0, al1, al2, al3;
        const uint32_t aaddr = Ah + (uint32_t)(((2 * s + kadd) * 16
                                    + 2 * w + radd) * 128) + inner;
        ldmx4(ah0, ah1, ah2, ah3, aaddr);
        ldmx4(al0, al1, al2, al3, aaddr + 32768);
#pragma unroll
        for (int j = 0; j < 8; j++) {
            const uint32_t baddr = Ah + 65536u
                + (uint32_t)(((2 * s + kadd) * 16 + 2 * j + radd) * 128) + inner;
            uint32_t h0, h1, h2, h3, l0, l1, l2, l3;
            ldmx4(h0, h1, h2, h3, baddr);
            ldmx4(l0, l1, l2, l3, baddr + 32768);
            mma_bf16(c[2 * j],     ah0, ah1, ah2, ah3, h0, h2);
            mma_bf16(c[2 * j],     al0, al1, al2, al3, h0, h2);
            mma_bf16(c[2 * j],     ah0, ah1, ah2, ah3, l0, l2);
            mma_bf16(c[2 * j + 1], ah0, ah1, ah2, ah3, h1, h3);
            mma_bf16(c[2 * j + 1], al0, al1, al2, al3, h1, h3);
            mma_bf16(c[2 * j + 1], ah0, ah1, ah2, ah3, l1, l3);
        }
    }

    // ---- epilogue: bf16 h rows + fused attention logits (R5/R6-verified) ----
    const int g = lane >> 2;
    const int t = lane & 3;
    const int rA = row0 + w * 16 + g;
    const int rB = rA + 8;
#pragma unroll
    for (int nf = 0; nf < 16; nf++) {
        const int col = nf * 8 + t * 2;
        if (rA < NN) {
            __nv_bfloat162 p = __floats2bfloat162_rn(c[nf][0], c[nf][1]);
            *(__nv_bfloat162*)&g_hb[rA * FD + col] = p;
        }
        if (rB < NN) {
            __nv_bfloat162 p = __floats2bfloat162_rn(c[nf][2], c[nf][3]);
            *(__nv_bfloat162*)&g_hb[rB * FD + col] = p;
        }
    }
#pragma unroll
    for (int h = 0; h < HH; h++) {
        float sA0 = 0.f, sD0 = 0.f, sA1 = 0.f, sD1 = 0.f;
#pragma unroll
        for (int q = 0; q < 4; q++) {
            const int nf  = h * 4 + q;
            const int col = nf * 8 + t * 2;
            const float a0 = as_w[col], a1 = as_w[col + 1];
            const float d0 = ad_w[col], d1 = ad_w[col + 1];
            sA0 += c[nf][0] * a0 + c[nf][1] * a1;
            sD0 += c[nf][0] * d0 + c[nf][1] * d1;
            sA1 += c[nf][2] * a0 + c[nf][3] * a1;
            sD1 += c[nf][2] * d0 + c[nf][3] * d1;
        }
        sA0 += __shfl_xor_sync(0xffffffffu, sA0, 1);
        sD0 += __shfl_xor_sync(0xffffffffu, sD0, 1);
        sA1 += __shfl_xor_sync(0xffffffffu, sA1, 1);
        sD1 += __shfl_xor_sync(0xffffffffu, sD1, 1);
        sA0 += __shfl_xor_sync(0xffffffffu, sA0, 2);
        sD0 += __shfl_xor_sync(0xffffffffu, sD0, 2);
        sA1 += __shfl_xor_sync(0xffffffffu, sA1, 2);
        sD1 += __shfl_xor_sync(0xffffffffu, sD1, 2);
        if (t == 0) {
            if (rA < NN) { g_as[rA * HH + h] = sA0; g_ad[rA * HH + h] = sD0; }
            if (rB < NN) { g_as[rB * HH + h] = sA1; g_ad[rB * HH + h] = sD1; }
        }
    }
}

// ---------------- K2: single-pass attention + aggregation + epilogue --------
__global__ __launch_bounds__(256) void k_attn(int last,
                           const float* __restrict__ bias,
                           const float* __restrict__ gamma,
                           const float* __restrict__ beta,
                           const float* __restrict__ mean,
                           const float* __restrict__ var,
                           const float* __restrict__ w_out,
                           const float* __restrict__ b_out,
                           float* __restrict__ out) {
    __shared__ float sw[8][32 * 4];
    __shared__ int   ssrc[8][32];
    const int n    = (blockIdx.x * blockDim.x + threadIdx.x) >> 5;
    const int wid  = threadIdx.x >> 5;
    const int lane = threadIdx.x & 31;
    if (n >= NN) return;
    const int rs = g_rs[n], re = g_rs[n + 1];
    const int head = lane >> 3;

    const float4 adv = *(const float4*)&g_ad[n * HH];
    const float4 asn = *(const float4*)&g_as[n * HH];

    const float ws0 = __expf(lrelu(asn.x + adv.x));
    const float ws1 = __expf(lrelu(asn.y + adv.y));
    const float ws2 = __expf(lrelu(asn.z + adv.z));
    const float ws3 = __expf(lrelu(asn.w + adv.w));
    const float w_self = (head == 0) ? ws0 : (head == 1) ? ws1 : (head == 2) ? ws2 : ws3;

    float4 acc;
    {
        const uint2 hv = *(const uint2*)&g_hb[n * FD + lane * 4];
        const float2 f0 = __bfloat1622float2(*(const __nv_bfloat162*)&hv.x);
        const float2 f1 = __bfloat1622float2(*(const __nv_bfloat162*)&hv.y);
        acc.x = f0.x * w_self; acc.y = f0.y * w_self;
        acc.z = f1.x * w_self; acc.w = f1.y * w_self;
    }

    float p0 = 0.f, p1 = 0.f, p2 = 0.f, p3 = 0.f;

    for (int base = rs; base < re; base += 32) {
        const int j = base + lane;
        float4 w = make_float4(0.f, 0.f, 0.f, 0.f);
        int sreg = 0;
        if (j < re) {
            sreg = g_csrc[j];
            const float4 as = *(const float4*)&g_as[sreg * HH];
            w.x = __expf(lrelu(as.x + adv.x));
            w.y = __expf(lrelu(as.y + adv.y));
            w.z = __expf(lrelu(as.z + adv.z));
            w.w = __expf(lrelu(as.w + adv.w));
            p0 += w.x; p1 += w.y; p2 += w.z; p3 += w.w;
        }
        __syncwarp();
        *(float4*)&sw[wid][lane * 4] = w;
        ssrc[wid][lane] = sreg;
        __syncwarp();
        const int cnt = min(32, re - base);
        int jj = 0;
        for (; jj + 4 <= cnt; jj += 4) {
            const int s0 = ssrc[wid][jj + 0];
            const int s1 = ssrc[wid][jj + 1];
            const int s2 = ssrc[wid][jj + 2];
            const int s3 = ssrc[wid][jj + 3];
            const float w0 = sw[wid][(jj + 0) * 4 + head];
            const float w1 = sw[wid][(jj + 1) * 4 + head];
            const float w2 = sw[wid][(jj + 2) * 4 + head];
            const float w3 = sw[wid][(jj + 3) * 4 + head];
            const uint2 v0 = *(const uint2*)&g_hb[s0 * FD + lane * 4];
            const uint2 v1 = *(const uint2*)&g_hb[s1 * FD + lane * 4];
            const uint2 v2 = *(const uint2*)&g_hb[s2 * FD + lane * 4];
            const uint2 v3 = *(const uint2*)&g_hb[s3 * FD + lane * 4];
            float2 a0 = __bfloat1622float2(*(const __nv_bfloat162*)&v0.x);
            float2 b0 = __bfloat1622float2(*(const __nv_bfloat162*)&v0.y);
            acc.x += a0.x * w0; acc.y += a0.y * w0; acc.z += b0.x * w0; acc.w += b0.y * w0;
            float2 a1 = __bfloat1622float2(*(const __nv_bfloat162*)&v1.x);
            float2 b1 = __bfloat1622float2(*(const __nv_bfloat162*)&v1.y);
            acc.x += a1.x * w1; acc.y += a1.y * w1; acc.z += b1.x * w1; acc.w += b1.y * w1;
            float2 a2 = __bfloat1622float2(*(const __nv_bfloat162*)&v2.x);
            float2 b2 = __bfloat1622float2(*(const __nv_bfloat162*)&v2.y);
            acc.x += a2.x * w2; acc.y += a2.y * w2; acc.z += b2.x * w2; acc.w += b2.y * w2;
            float2 a3 = __bfloat1622float2(*(const __nv_bfloat162*)&v3.x);
            float2 b3 = __bfloat1622float2(*(const __nv_bfloat162*)&v3.y);
            acc.x += a3.x * w3; acc.y += a3.y * w3; acc.z += b3.x * w3; acc.w += b3.y * w3;
        }
        for (; jj < cnt; jj++) {
            const int   s  = ssrc[wid][jj];
            const float ww = sw[wid][jj * 4 + head];
            const uint2 v  = *(const uint2*)&g_hb[s * FD + lane * 4];
            float2 a = __bfloat1622float2(*(const __nv_bfloat162*)&v.x);
            float2 b = __bfloat1622float2(*(const __nv_bfloat162*)&v.y);
            acc.x += a.x * ww; acc.y += a.y * ww;
            acc.z += b.x * ww; acc.w += b.y * ww;
        }
    }

#pragma unroll
    for (int o = 16; o > 0; o >>= 1) {
        p0 += __shfl_xor_sync(0xffffffffu, p0, o);
        p1 += __shfl_xor_sync(0xffffffffu, p1, o);
        p2 += __shfl_xor_sync(0xffffffffu, p2, o);
        p3 += __shfl_xor_sync(0xffffffffu, p3, o);
    }
    const float denom = ((head == 0) ? p0 : (head == 1) ? p1 : (head == 2) ? p2 : p3)
                        + w_self;
    const float inv = 1.f / (denom + 1e-16f);
    acc.x *= inv; acc.y *= inv; acc.z *= inv; acc.w *= inv;

    const int c4 = lane * 4;
    const float4 b  = *(const float4*)&bias[c4];
    const float4 g  = *(const float4*)&gamma[c4];
    const float4 bt = *(const float4*)&beta[c4];
    const float4 mm = *(const float4*)&mean[c4];
    const float4 vr = *(const float4*)&var[c4];
    float4 o;
    o.x = fmaxf((acc.x + b.x - mm.x) * rsqrtf(vr.x + BNEPS) * g.x + bt.x, 0.f);
    o.y = fmaxf((acc.y + b.y - mm.y) * rsqrtf(vr.y + BNEPS) * g.y + bt.y, 0.f);
    o.z = fmaxf((acc.z + b.z - mm.z) * rsqrtf(vr.z + BNEPS) * g.z + bt.z, 0.f);
    o.w = fmaxf((acc.w + b.w - mm.w) * rsqrtf(vr.w + BNEPS) * g.w + bt.w, 0.f);

    if (!last) {
        *(float4*)&g_x[n * FD + c4] = o;
    } else {
        const float4 wv = *(const float4*)&w_out[c4];
        float sum = o.x * wv.x + o.y * wv.y + o.z * wv.z + o.w * wv.w;
#pragma unroll
        for (int off = 16; off > 0; off >>= 1)
            sum += __shfl_down_sync(0xffffffffu, sum, off);
        if (lane == 0) out[n] = sum + b_out[0];
    }
}

// ---------------- launcher ---------------------------------------------------
extern "C" void kernel_launch(void* const* d_in, const int* in_sizes, int n_in,
                              void* d_out, int out_size) {
    static cudaStream_t s2 = nullptr;
    static cudaEvent_t  evf = nullptr, evj = nullptr;
    if (s2 == nullptr) {
        cudaStreamCreateWithFlags(&s2, cudaStreamNonBlocking);
        cudaEventCreateWithFlags(&evf, cudaEventDisableTiming);
        cudaEventCreateWithFlags(&evj, cudaEventDisableTiming);
        cudaFuncSetAttribute(k_gemm, cudaFuncAttributeMaxDynamicSharedMemorySize,
                             131072);
    }

    const float* x       = (const float*)d_in[0];
    const int*   ei      = (const int*)  d_in[1];
    const float* W       = (const float*)d_in[2];
    const float* att_src = (const float*)d_in[3];
    const float* att_dst = (const float*)d_in[4];
    const float* bias    = (const float*)d_in[5];
    const float* gamma   = (const float*)d_in[6];
    const float* beta    = (const float*)d_in[7];
    const float* mean    = (const float*)d_in[8];
    const float* var     = (const float*)d_in[9];
    const float* w_out   = (const float*)d_in[10];
    const float* b_out   = (const float*)d_in[11];

    const int* src = ei;
    const int* dst = ei + EE;

    const int WGRID = (NN * 32 + 255) / 256;
    const int GGRID = (NN + 127) / 128;   // 313

    // fork: CSR chain on s2, concurrent with prep + layer-0 GEMM on main
    cudaEventRecord(evf, 0);
    cudaStreamWaitEvent(s2, evf, 0);
    k_zero_cnt<<<(NN + 255) / 256, 256, 0, s2>>>();
    k_hist    <<<(EE / 4 + 255) / 256, 256, 0, s2>>>(dst);
    k_scan    <<<1, 1024, 0, s2>>>();
    k_scatter <<<(EE / 4 + 255) / 256, 256, 0, s2>>>(src, dst);
    cudaEventRecord(evj, s2);

    k_prep<<<(LL * FD * FD + 255) / 256, 256>>>(W);
    k_gemm<<<GGRID, 256, 131072>>>(x, 0, att_src, att_dst);

    cudaStreamWaitEvent(0, evj, 0);

    for (int l = 0; l < LL; l++) {
        if (l > 0)
            k_gemm<<<GGRID, 256, 131072>>>(x, l, att_src + l * FD, att_dst + l * FD);
        k_attn<<<WGRID, 256>>>(l == LL - 1,
                               bias + l * FD, gamma + l * FD, beta + l * FD,
                               mean + l * FD, var + l * FD,
                               w_out, b_out, (float*)d_out);
    }
}